// round 1
// baseline (speedup 1.0000x reference)
#include <cuda_runtime.h>
#include <cuda_bf16.h>

#define HIMG 240
#define WIMG 135
#define HW   (HIMG * WIMG)
#define NF   1000
#define NV   600
#define INV_SIGMA 1.0e4f
// log(1/1e-4 - 1) * 1e-4
#define BLURF 9.210240366975849e-4f

struct __align__(16) FaceData {
    float ax, ay, bx, by, cx, cy;
    float e0x, e0y, e1x, e1y, e2x, e2y;
    float rd0, rd1, rd2;
    int x0, x1, y0, y1;   // inclusive pixel ranges; x0 > x1 => skip face
};

__device__ FaceData g_face[NF];
__device__ float    g_sum[HW];

// ---------------------------------------------------------------------------
// Kernel 1: zero per-pixel accumulator + loss slot
// ---------------------------------------------------------------------------
__global__ void zero_kernel(float* lossp) {
    int i = blockIdx.x * blockDim.x + threadIdx.x;
    if (i < HW) g_sum[i] = 0.0f;
    if (i == 0 && lossp) *lossp = 0.0f;
}

// ---------------------------------------------------------------------------
// Kernel 2: per-face setup (projection, edges, reciprocal denoms, bbox)
// ---------------------------------------------------------------------------
__global__ void prep_kernel(const float* __restrict__ verts,
                            const int* __restrict__ faces) {
    int f = blockIdx.x * blockDim.x + threadIdx.x;
    if (f >= NF) return;

    int idx[3];
    idx[0] = faces[3 * f + 0];
    idx[1] = faces[3 * f + 1];
    idx[2] = faces[3 * f + 2];

    float Px[3], Py[3], zs[3];
#pragma unroll
    for (int k = 0; k < 3; k++) {
        float x = verts[3 * idx[k] + 0];
        float y = verts[3 * idx[k] + 1];
        float z = verts[3 * idx[k] + 2];
        // v = verts @ R.T  with R = [[-1,0,0],[0,-1,0],[0,0,1]]
        float vx = -x, vy = -y, vz = z;
        zs[k] = vz;
        float zz = fmaxf(vz, 1e-6f);
        Px[k] = (1000.0f * vx / zz + 512.0f) / 1024.0f * (float)WIMG;
        Py[k] = (1000.0f * vy / zz + 512.0f) / 1024.0f * (float)HIMG;
    }
    float tz = (zs[0] + zs[1] + zs[2]) * (1.0f / 3.0f);

    FaceData fd;
    fd.ax = Px[0]; fd.ay = Py[0];
    fd.bx = Px[1]; fd.by = Py[1];
    fd.cx = Px[2]; fd.cy = Py[2];
    fd.e0x = fd.bx - fd.ax; fd.e0y = fd.by - fd.ay;
    fd.e1x = fd.cx - fd.bx; fd.e1y = fd.cy - fd.by;
    fd.e2x = fd.ax - fd.cx; fd.e2y = fd.ay - fd.cy;
    fd.rd0 = 1.0f / (fd.e0x * fd.e0x + fd.e0y * fd.e0y + 1e-12f);
    fd.rd1 = 1.0f / (fd.e1x * fd.e1x + fd.e1y * fd.e1y + 1e-12f);
    fd.rd2 = 1.0f / (fd.e2x * fd.e2x + fd.e2y * fd.e2y + 1e-12f);

    if (!(tz > 1e-6f)) {
        fd.x0 = 1; fd.x1 = 0; fd.y0 = 1; fd.y1 = 0;   // skip
    } else {
        float minx = fminf(fd.ax, fminf(fd.bx, fd.cx));
        float maxx = fmaxf(fd.ax, fmaxf(fd.bx, fd.cx));
        float miny = fminf(fd.ay, fminf(fd.by, fd.cy));
        float maxy = fmaxf(fd.ay, fmaxf(fd.by, fd.cy));
        int x0 = max(0, (int)floorf(minx) - 1);
        int x1 = min(WIMG - 1, (int)ceilf(maxx));
        int y0 = max(0, (int)floorf(miny) - 1);
        int y1 = min(HIMG - 1, (int)ceilf(maxy));
        // Fully degenerate (point) triangle: all crosses are 0 everywhere in
        // the reference => "inside" over the whole image. Rasterize it all.
        bool pointdeg = (fd.e0x == 0.0f && fd.e0y == 0.0f &&
                         fd.e1x == 0.0f && fd.e1y == 0.0f);
        if (pointdeg) { x0 = 0; x1 = WIMG - 1; y0 = 0; y1 = HIMG - 1; }
        fd.x0 = x0; fd.x1 = x1; fd.y0 = y0; fd.y1 = y1;
    }
    g_face[f] = fd;
}

// ---------------------------------------------------------------------------
// Kernel 3: face-major rasterizer. One block per face; threads sweep bbox.
// Accumulates log1p(1 - prob) = -softplus(-signed_d2 / sigma) per pixel.
// ---------------------------------------------------------------------------
__global__ void raster_kernel() {
    const FaceData fd = g_face[blockIdx.x];
    int w = fd.x1 - fd.x0 + 1;
    int h = fd.y1 - fd.y0 + 1;
    if (w <= 0 || h <= 0) return;
    int n = w * h;

    for (int i = threadIdx.x; i < n; i += blockDim.x) {
        int ix = fd.x0 + (i % w);
        int iy = fd.y0 + (i / w);
        float px = (float)ix + 0.5f;
        float py = (float)iy + 0.5f;

        float apx0 = px - fd.ax, apy0 = py - fd.ay;
        float apx1 = px - fd.bx, apy1 = py - fd.by;
        float apx2 = px - fd.cx, apy2 = py - fd.cy;

        float c0 = fd.e0x * apy0 - fd.e0y * apx0;
        float c1 = fd.e1x * apy1 - fd.e1y * apx1;
        float c2 = fd.e2x * apy2 - fd.e2y * apx2;
        bool inside = (c0 >= 0.0f && c1 >= 0.0f && c2 >= 0.0f) ||
                      (c0 <= 0.0f && c1 <= 0.0f && c2 <= 0.0f);

        float t0 = fminf(fmaxf((apx0 * fd.e0x + apy0 * fd.e0y) * fd.rd0, 0.0f), 1.0f);
        float rx = apx0 - t0 * fd.e0x;
        float ry = apy0 - t0 * fd.e0y;
        float d2min = rx * rx + ry * ry;

        float t1 = fminf(fmaxf((apx1 * fd.e1x + apy1 * fd.e1y) * fd.rd1, 0.0f), 1.0f);
        rx = apx1 - t1 * fd.e1x;
        ry = apy1 - t1 * fd.e1y;
        d2min = fminf(d2min, rx * rx + ry * ry);

        float t2 = fminf(fmaxf((apx2 * fd.e2x + apy2 * fd.e2y) * fd.rd2, 0.0f), 1.0f);
        rx = apx2 - t2 * fd.e2x;
        ry = apy2 - t2 * fd.e2y;
        d2min = fminf(d2min, rx * rx + ry * ry);

        if (inside || d2min <= BLURF) {
            float u = (inside ? d2min : -d2min) * INV_SIGMA;
            // log1p(-sigmoid(u)) == -softplus(u)
            float sp = (u > 15.0f) ? u : log1pf(__expf(u));
            if (sp != 0.0f) atomicAdd(&g_sum[iy * WIMG + ix], -sp);
        }
    }
}

// ---------------------------------------------------------------------------
// Kernel 4: alpha = 1 - exp(sum); write sil; reduce mean |alpha - gt| -> loss
// ---------------------------------------------------------------------------
__global__ void finalize_kernel(const float* __restrict__ gt,
                                float* __restrict__ sil,
                                float* lossp) {
    int i = blockIdx.x * blockDim.x + threadIdx.x;
    float local = 0.0f;
    if (i < HW) {
        float s = g_sum[i];
        float alpha = 1.0f - expf(s);
        sil[i] = alpha;
        local = fabsf(alpha - gt[i]);
    }
#pragma unroll
    for (int o = 16; o > 0; o >>= 1)
        local += __shfl_down_sync(0xffffffffu, local, o);

    __shared__ float ws[8];
    int lane = threadIdx.x & 31;
    int wid  = threadIdx.x >> 5;
    if (lane == 0) ws[wid] = local;
    __syncthreads();
    if (wid == 0) {
        int nw = (blockDim.x + 31) >> 5;
        local = (lane < nw) ? ws[lane] : 0.0f;
#pragma unroll
        for (int o = 4; o > 0; o >>= 1)
            local += __shfl_down_sync(0xffu, local, o);
        if (lane == 0 && lossp)
            atomicAdd(lossp, local * (1.0f / (float)HW));
    }
}

// ---------------------------------------------------------------------------
extern "C" void kernel_launch(void* const* d_in, const int* in_sizes, int n_in,
                              void* d_out, int out_size) {
    const float* verts = nullptr;
    const float* gt    = nullptr;
    const int*   faces = nullptr;
    for (int i = 0; i < n_in; i++) {
        if (in_sizes[i] == NV * 3)      verts = (const float*)d_in[i];
        else if (in_sizes[i] == HW)     gt    = (const float*)d_in[i];
        else if (in_sizes[i] == NF * 3) faces = (const int*)d_in[i];
    }

    float* out   = (float*)d_out;
    int    off   = out_size - HW;               // expect 1 (loss scalar first)
    float* lossp = (off >= 1) ? out : nullptr;
    float* sil   = out + (off >= 1 ? off : 0);

    zero_kernel<<<(HW + 255) / 256, 256>>>(lossp);
    prep_kernel<<<(NF + 127) / 128, 128>>>(verts, faces);
    raster_kernel<<<NF, 256>>>();
    finalize_kernel<<<(HW + 255) / 256, 256>>>(gt, sil, lossp);
}